// round 12
// baseline (speedup 1.0000x reference)
#include <cuda_runtime.h>
#include <cstdint>

// ---------------- problem constants ----------------
#define H 128
#define W 128
#define C 256
#define O 256
#define KH 3
#define KW 3
#define OH 126
#define OW 126

#define NNZ_PAD 2304          // 2048 + 256 (buckets padded to EVEN length)

// ---------------- tiling ----------------
#define TH 4            // output rows per block
#define TW 32           // output cols per block
#define ROWS (TH + 2)   // input rows needed = 6
#define XT (TW + 2)     // input x-positions needed = 34
#define XP 34           // x-pitch (MUST be >= XT)
#define TWP 33          // x-pitch for output staging (conflict-free)
#define RPITCH (C * XP) // row pitch in s_in (floats) = 8704

#define S_IN_FLOATS (ROWS * C * XP)                  // 52224 floats = 208896 B
#define SMEM_BYTES  (S_IN_FLOATS * 4 + NNZ_PAD * 8)  // 227328 B dynamic
// static: s_off 1028 + s_cnt 1024 + s_cur 1024 = 3076
// total 230404 B < 232448 B cap.

// ============================================================
// Single fused kernel: 1024 threads, CTA = [4 x 32] tile, all 256 o.
//   phase 0: in-CTA CSR build from raw COO, overlapped with staging
//   phase 2: 8 o per warp, lane = x, 4-entry iterations (4 chains)
//   phase 3: transpose via smem reuse -> coalesced STG
// ============================================================
__global__ void __launch_bounds__(1024, 1)
sparse_conv_kernel(const float* __restrict__ in,
                   const int4* __restrict__ wi4,
                   const float* __restrict__ wv,
                   float* __restrict__ out, int nnz)
{
    extern __shared__ float smem[];
    float* s_in  = smem;                              // 52224 floats
    uint2* s_csr = (uint2*)(smem + S_IN_FLOATS);      // 2304 entries
    __shared__ int s_off[O + 1];
    __shared__ int s_cnt[O];
    __shared__ int s_cur[O];

    const int tid    = threadIdx.x;
    const int warpId = tid >> 5;
    const int lane   = tid & 31;

    const int x0 = blockIdx.x * TW;
    const int y0 = blockIdx.y * TH;
    const int bz = blockIdx.z;

    // ---- phase 0a: zero counters; fetch my COO entries into regs ----
    if (tid < O) { s_cnt[tid] = 0; s_cur[tid] = 0; }

    int4  w0 = make_int4(0, 0, 0, 0), w1 = w0;
    float v0 = 0.0f, v1 = 0.0f;
    const bool h0 = (tid < nnz);
    const bool h1 = (tid + 1024 < nnz);
    if (h0) { w0 = wi4[tid];        v0 = wv[tid]; }
    if (h1) { w1 = wi4[tid + 1024]; v1 = wv[tid + 1024]; }
    __syncthreads();                       // zeroing visible

    // ---- phase 0b: count buckets ----
    if (h0) atomicAdd(&s_cnt[w0.x], 1);
    if (h1) atomicAdd(&s_cnt[w1.x], 1);

    // ---- phase 1b (overlapped): stage input tile [row][c][x] ----
    // ROWS*XT = 204 pixels, 32 warps -> 7 iterations (last partial)
#pragma unroll
    for (int t = 0; t < 7; t++) {
        int p = warpId + (t << 5);
        if (p < ROWS * XT) {
            int rr = p / XT;
            int xx = p - rr * XT;
            int iy = y0 + rr;
            int ix = x0 + xx;
            float* sb = s_in + (rr * C + lane) * XP + xx;
            if ((iy < H) && (ix < W)) {
                const float* gb = in + (((bz * H + iy) * W + ix) * C) + lane;
                float v[8];
#pragma unroll
                for (int cg = 0; cg < 8; cg++) v[cg] = gb[cg * 32];
#pragma unroll
                for (int cg = 0; cg < 8; cg++) sb[cg * 32 * XP] = v[cg];
            } else {
#pragma unroll
                for (int cg = 0; cg < 8; cg++) sb[cg * 32 * XP] = 0.0f;
            }
        }
    }
    __syncthreads();                       // counts complete (staging too)

    // ---- phase 0c: exclusive scan of 256 even-padded counts (warp 0) ----
    if (tid < 32) {
        int base = tid * 8;
        int loc[8], run = 0;
#pragma unroll
        for (int j = 0; j < 8; j++) {
            int c = (s_cnt[base + j] + 1) & ~1;   // pad to even
            loc[j] = run; run += c;
        }
        int incl = run;
#pragma unroll
        for (int d = 1; d < 32; d <<= 1) {
            int n = __shfl_up_sync(0xffffffffu, incl, d);
            if (tid >= d) incl += n;
        }
        int excl = incl - run;
#pragma unroll
        for (int j = 0; j < 8; j++) s_off[base + j] = excl + loc[j];
        if (tid == 31) s_off[O] = incl;
    }
    __syncthreads();                       // s_off ready

    // ---- phase 0d: scatter entries (with reference flatten-mismatch remap) ----
    if (h0) {
        int k  = w0.y * (KW * C) + w0.z * C + w0.w;  // flat idx in W.reshape(O,-1)
        int ce = k / 9;
        int t  = k - 9 * ce;
        int dy = t / 3;
        int dx = t - 3 * dy;
        int off = (dy * C + ce) * XP + dx;
        int pos = s_off[w0.x] + atomicAdd(&s_cur[w0.x], 1);
        s_csr[pos] = make_uint2((unsigned)off, __float_as_uint(v0));
    }
    if (h1) {
        int k  = w1.y * (KW * C) + w1.z * C + w1.w;
        int ce = k / 9;
        int t  = k - 9 * ce;
        int dy = t / 3;
        int dx = t - 3 * dy;
        int off = (dy * C + ce) * XP + dx;
        int pos = s_off[w1.x] + atomicAdd(&s_cur[w1.x], 1);
        s_csr[pos] = make_uint2((unsigned)off, __float_as_uint(v1));
    }
    // zero the (at most one) pad slot per bucket
    if (tid < O) {
        int c = s_cnt[tid];
        if (c & 1) s_csr[s_off[tid] + c] = make_uint2(0u, 0u);
    }
    __syncthreads();                       // CSR ready

    // ---- phase 2: gather-accumulate, 8 o per warp, lane = x ----
    // 4 entries per main iteration: 2x LDS.128 csr (broadcast) +
    // 16 data LDS + 16 FMA in 4 independent chains; tail = one pair.
    const int oBase = warpId * 8;
    const float* s_in_lane = s_in + lane;
    float acc[8][TH];
#pragma unroll
    for (int oo = 0; oo < 8; oo++)
#pragma unroll
        for (int r = 0; r < TH; r++) acc[oo][r] = 0.0f;

#pragma unroll
    for (int oo = 0; oo < 8; oo++) {
        const int k0 = s_off[oBase + oo];
        const int k1 = s_off[oBase + oo + 1];
        int k = k0;
        for (; k + 4 <= k1; k += 4) {
            uint4 eA = *(const uint4*)(s_csr + k);
            uint4 eB = *(const uint4*)(s_csr + k + 2);
            const float* a0 = s_in_lane + eA.x;
            const float* a1 = s_in_lane + eA.z;
            const float* a2 = s_in_lane + eB.x;
            const float* a3 = s_in_lane + eB.z;
            const float f0 = __uint_as_float(eA.y);
            const float f1 = __uint_as_float(eA.w);
            const float f2 = __uint_as_float(eB.y);
            const float f3 = __uint_as_float(eB.w);
#pragma unroll
            for (int r = 0; r < TH; r++) acc[oo][r] = fmaf(f0, a0[r * RPITCH], acc[oo][r]);
#pragma unroll
            for (int r = 0; r < TH; r++) acc[oo][r] = fmaf(f1, a1[r * RPITCH], acc[oo][r]);
#pragma unroll
            for (int r = 0; r < TH; r++) acc[oo][r] = fmaf(f2, a2[r * RPITCH], acc[oo][r]);
#pragma unroll
            for (int r = 0; r < TH; r++) acc[oo][r] = fmaf(f3, a3[r * RPITCH], acc[oo][r]);
        }
        if (k < k1) {   // exactly one pair left (buckets are even)
            uint4 eA = *(const uint4*)(s_csr + k);
            const float* a0 = s_in_lane + eA.x;
            const float* a1 = s_in_lane + eA.z;
            const float f0 = __uint_as_float(eA.y);
            const float f1 = __uint_as_float(eA.w);
#pragma unroll
            for (int r = 0; r < TH; r++) acc[oo][r] = fmaf(f0, a0[r * RPITCH], acc[oo][r]);
#pragma unroll
            for (int r = 0; r < TH; r++) acc[oo][r] = fmaf(f1, a1[r * RPITCH], acc[oo][r]);
        }
    }
    __syncthreads();   // s_in dead -> reuse

    // ---- phase 3: transpose-stage and coalesced store ----
    float* s_out = s_in;  // [r][o][x], pitch TWP=33 (33792 <= 52224 floats)
#pragma unroll
    for (int oo = 0; oo < 8; oo++) {
        int o = oBase + oo;
#pragma unroll
        for (int r = 0; r < TH; r++)
            s_out[(r * O + o) * TWP + lane] = acc[oo][r];
    }
    __syncthreads();

    const int och  = tid & 255;
    const int pgrp = tid >> 8;             // 0..3
    const int obase32 = ((bz * OH + y0) * OW + x0) * O + och;
#pragma unroll
    for (int i = 0; i < 32; i++) {
        int p  = pgrp + (i << 2);          // 0..127
        int r  = p >> 5;
        int xx = p & 31;
        int gy = y0 + r;
        int gx = x0 + xx;
        if (gy < OH && gx < OW)
            out[obase32 + (r * OW + xx) * O] =
                s_out[(r * O + och) * TWP + xx];
    }
}

// ============================================================
extern "C" void kernel_launch(void* const* d_in, const int* in_sizes, int n_in,
                              void* d_out, int out_size)
{
    const float* in  = (const float*)d_in[0];
    const int4*  wi4 = (const int4*)d_in[1];   // int32 indices, 4 per entry
    const float* wv  = (const float*)d_in[2];
    float*       out = (float*)d_out;

    int nnz = in_sizes[2];
    if (nnz > 2048) nnz = 2048;
    int B = in_sizes[0] / (H * W * C);

    cudaFuncSetAttribute(sparse_conv_kernel,
                         cudaFuncAttributeMaxDynamicSharedMemorySize, SMEM_BYTES);

    dim3 grid((OW + TW - 1) / TW, (OH + TH - 1) / TH, B);   // 4 x 32 x B
    sparse_conv_kernel<<<grid, 1024, SMEM_BYTES>>>(in, wi4, wv, out, nnz);
}

// round 13
// speedup vs baseline: 1.0381x; 1.0381x over previous
#include <cuda_runtime.h>
#include <cstdint>

// ---------------- problem constants ----------------
#define H 128
#define W 128
#define C 256
#define O 256
#define KH 3
#define KW 3
#define OH 126
#define OW 126

#define NNZ_PAD 2304          // 2048 + 256 (buckets padded to EVEN length)

// ---------------- tiling ----------------
#define TH 4            // output rows per block
#define TW 32           // output cols per block
#define ROWS (TH + 2)   // input rows needed = 6
#define XT (TW + 2)     // input x-positions needed = 34
#define XP 34           // x-pitch (MUST be >= XT)
#define TWP 33          // x-pitch for output staging (conflict-free)
#define RPITCH (C * XP) // row pitch in s_in (floats) = 8704

#define S_IN_FLOATS (ROWS * C * XP)                  // 52224 floats = 208896 B
#define SMEM_BYTES  (S_IN_FLOATS * 4 + NNZ_PAD * 8)  // 227328 B dynamic
// static: s_off 1028 + s_cnt 1024 + s_cur 1024 = 3076
// total 230404 B < 232448 B cap.

// ============================================================
// Single fused kernel: 1024 threads, CTA = [4 x 32] tile, all 256 o,
// TWO batches per CTA (CSR built once, reused).
//   phase 0: in-CTA CSR build from raw COO
//   per batch: stage input -> gather-accumulate -> transpose-store
// ============================================================
__global__ void __launch_bounds__(1024, 1)
sparse_conv_kernel(const float* __restrict__ in,
                   const int4* __restrict__ wi4,
                   const float* __restrict__ wv,
                   float* __restrict__ out, int nnz)
{
    extern __shared__ float smem[];
    float* s_in  = smem;                              // 52224 floats
    uint2* s_csr = (uint2*)(smem + S_IN_FLOATS);      // 2304 entries
    __shared__ int s_off[O + 1];
    __shared__ int s_cnt[O];
    __shared__ int s_cur[O];

    const int tid    = threadIdx.x;
    const int warpId = tid >> 5;
    const int lane   = tid & 31;

    const int x0  = blockIdx.x * TW;
    const int y0  = blockIdx.y * TH;
    const int bz0 = blockIdx.z * 2;       // this CTA handles bz0 and bz0+1

    // ---- phase 0: build CSR in smem (once per CTA) ----
    if (tid < O) { s_cnt[tid] = 0; s_cur[tid] = 0; }

    int4  w0 = make_int4(0, 0, 0, 0), w1 = w0;
    float v0 = 0.0f, v1 = 0.0f;
    const bool h0 = (tid < nnz);
    const bool h1 = (tid + 1024 < nnz);
    if (h0) { w0 = wi4[tid];        v0 = wv[tid]; }
    if (h1) { w1 = wi4[tid + 1024]; v1 = wv[tid + 1024]; }
    __syncthreads();                       // zeroing visible

    if (h0) atomicAdd(&s_cnt[w0.x], 1);
    if (h1) atomicAdd(&s_cnt[w1.x], 1);
    __syncthreads();                       // counts complete

    // exclusive scan of 256 even-padded counts (warp 0)
    if (tid < 32) {
        int base = tid * 8;
        int loc[8], run = 0;
#pragma unroll
        for (int j = 0; j < 8; j++) {
            int c = (s_cnt[base + j] + 1) & ~1;   // pad to even
            loc[j] = run; run += c;
        }
        int incl = run;
#pragma unroll
        for (int d = 1; d < 32; d <<= 1) {
            int n = __shfl_up_sync(0xffffffffu, incl, d);
            if (tid >= d) incl += n;
        }
        int excl = incl - run;
#pragma unroll
        for (int j = 0; j < 8; j++) s_off[base + j] = excl + loc[j];
        if (tid == 31) s_off[O] = incl;
    }
    __syncthreads();                       // s_off ready

    // scatter entries (with reference flatten-mismatch remap)
    if (h0) {
        int k  = w0.y * (KW * C) + w0.z * C + w0.w;  // flat idx in W.reshape(O,-1)
        int ce = k / 9;
        int t  = k - 9 * ce;
        int dy = t / 3;
        int dx = t - 3 * dy;
        int off = (dy * C + ce) * XP + dx;
        int pos = s_off[w0.x] + atomicAdd(&s_cur[w0.x], 1);
        s_csr[pos] = make_uint2((unsigned)off, __float_as_uint(v0));
    }
    if (h1) {
        int k  = w1.y * (KW * C) + w1.z * C + w1.w;
        int ce = k / 9;
        int t  = k - 9 * ce;
        int dy = t / 3;
        int dx = t - 3 * dy;
        int off = (dy * C + ce) * XP + dx;
        int pos = s_off[w1.x] + atomicAdd(&s_cur[w1.x], 1);
        s_csr[pos] = make_uint2((unsigned)off, __float_as_uint(v1));
    }
    if (tid < O) {                          // zero the pad slot per bucket
        int c = s_cnt[tid];
        if (c & 1) s_csr[s_off[tid] + c] = make_uint2(0u, 0u);
    }
    // (sync happens at top of batch loop, after staging stores are issued)

    const int oBase = warpId * 8;
    const float* s_in_lane = s_in + lane;

    // ================= per-batch loop =================
    for (int bi = 0; bi < 2; bi++) {
        const int bz = bz0 + bi;

        // ---- stage input tile [row][c][x], one pixel/warp-iter ----
        // ROWS*XT = 204 pixels, 32 warps -> 7 iterations (last partial)
#pragma unroll
        for (int t = 0; t < 7; t++) {
            int p = warpId + (t << 5);
            if (p < ROWS * XT) {
                int rr = p / XT;
                int xx = p - rr * XT;
                int iy = y0 + rr;
                int ix = x0 + xx;
                float* sb = s_in + (rr * C + lane) * XP + xx;
                if ((iy < H) && (ix < W)) {
                    const float* gb = in + (((bz * H + iy) * W + ix) * C) + lane;
                    float v[8];
#pragma unroll
                    for (int cg = 0; cg < 8; cg++) v[cg] = gb[cg * 32];
#pragma unroll
                    for (int cg = 0; cg < 8; cg++) sb[cg * 32 * XP] = v[cg];
                } else {
#pragma unroll
                    for (int cg = 0; cg < 8; cg++) sb[cg * 32 * XP] = 0.0f;
                }
            }
        }
        __syncthreads();     // CSR (first iter) + staged tile ready

        // ---- gather-accumulate: 8 o per warp, lane = x ----
        float acc[8][TH];
#pragma unroll
        for (int oo = 0; oo < 8; oo++)
#pragma unroll
            for (int r = 0; r < TH; r++) acc[oo][r] = 0.0f;

#pragma unroll
        for (int oo = 0; oo < 8; oo++) {
            const int k0 = s_off[oBase + oo];
            const int k1 = s_off[oBase + oo + 1];
#pragma unroll 2
            for (int k = k0; k < k1; k += 2) {
                uint4 e = *(const uint4*)(s_csr + k);    // 2 entries, 16B aligned
                const float* a0 = s_in_lane + e.x;
                const float* a1 = s_in_lane + e.z;
                float d0[TH], d1[TH];
#pragma unroll
                for (int r = 0; r < TH; r++) d0[r] = a0[r * RPITCH];
#pragma unroll
                for (int r = 0; r < TH; r++) d1[r] = a1[r * RPITCH];
                const float f0 = __uint_as_float(e.y);
                const float f1 = __uint_as_float(e.w);
#pragma unroll
                for (int r = 0; r < TH; r++) acc[oo][r] = fmaf(f0, d0[r], acc[oo][r]);
#pragma unroll
                for (int r = 0; r < TH; r++) acc[oo][r] = fmaf(f1, d1[r], acc[oo][r]);
            }
        }
        __syncthreads();   // s_in dead -> reuse for transpose

        // ---- transpose-stage and coalesced store ----
        float* s_out = s_in;  // [r][o][x], pitch TWP=33
#pragma unroll
        for (int oo = 0; oo < 8; oo++) {
            int o = oBase + oo;
#pragma unroll
            for (int r = 0; r < TH; r++)
                s_out[(r * O + o) * TWP + lane] = acc[oo][r];
        }
        __syncthreads();

        const int och  = tid & 255;
        const int pgrp = tid >> 8;             // 0..3
        const int obase32 = ((bz * OH + y0) * OW + x0) * O + och;
#pragma unroll
        for (int i = 0; i < 32; i++) {
            int p  = pgrp + (i << 2);          // 0..127
            int r  = p >> 5;
            int xx = p & 31;
            int gy = y0 + r;
            int gx = x0 + xx;
            if (gy < OH && gx < OW)
                out[obase32 + (r * OW + xx) * O] =
                    s_out[(r * O + och) * TWP + xx];
        }
        __syncthreads();   // s_out dead before next batch's staging
    }
}

// ============================================================
extern "C" void kernel_launch(void* const* d_in, const int* in_sizes, int n_in,
                              void* d_out, int out_size)
{
    const float* in  = (const float*)d_in[0];
    const int4*  wi4 = (const int4*)d_in[1];   // int32 indices, 4 per entry
    const float* wv  = (const float*)d_in[2];
    float*       out = (float*)d_out;

    int nnz = in_sizes[2];
    if (nnz > 2048) nnz = 2048;
    int B = in_sizes[0] / (H * W * C);
    int Bz = (B + 1) / 2;                      // 2 batches per CTA

    cudaFuncSetAttribute(sparse_conv_kernel,
                         cudaFuncAttributeMaxDynamicSharedMemorySize, SMEM_BYTES);

    dim3 grid((OW + TW - 1) / TW, (OH + TH - 1) / TH, Bz);  // 4 x 32 x 2
    sparse_conv_kernel<<<grid, 1024, SMEM_BYTES>>>(in, wi4, wv, out, nnz);
}

// round 14
// speedup vs baseline: 1.0635x; 1.0245x over previous
#include <cuda_runtime.h>
#include <cstdint>

// ---------------- problem constants ----------------
#define H 128
#define W 128
#define C 256
#define O 256
#define KH 3
#define KW 3
#define OH 126
#define OW 126

#define NNZ_PAD 2304          // 2048 + 256 (buckets padded to EVEN length)

// ---------------- tiling ----------------
#define TH 4            // output rows per block
#define TW 32           // output cols per block
#define ROWS (TH + 2)   // input rows needed = 6
#define XT (TW + 2)     // input x-positions needed = 34
#define XP 34           // x-pitch (MUST be >= XT)
#define TWP 33          // x-pitch for output staging (conflict-free)
#define RPITCH (C * XP) // row pitch in s_in (floats) = 8704

#define S_IN_FLOATS (ROWS * C * XP)                  // 52224 floats = 208896 B
#define SMEM_BYTES  (S_IN_FLOATS * 4 + NNZ_PAD * 8)  // 227328 B dynamic
// static: s_off 1028 + s_cnt 1024 + s_cur 1024 = 3076
// total 230404 B < 232448 B cap.

// ============================================================
// Single fused persistent kernel: 1024 threads, grid = 4x32 = 128 CTAs
// (single wave on 148 SMs). CTA = [4 x 32] tile, all 256 o, loops over
// ALL batches with the CSR built once.
//   phase 0: in-CTA CSR build from raw COO
//   per batch: stage input -> gather-accumulate -> transpose-store
// ============================================================
__global__ void __launch_bounds__(1024, 1)
sparse_conv_kernel(const float* __restrict__ in,
                   const int4* __restrict__ wi4,
                   const float* __restrict__ wv,
                   float* __restrict__ out, int nnz, int B)
{
    extern __shared__ float smem[];
    float* s_in  = smem;                              // 52224 floats
    uint2* s_csr = (uint2*)(smem + S_IN_FLOATS);      // 2304 entries
    __shared__ int s_off[O + 1];
    __shared__ int s_cnt[O];
    __shared__ int s_cur[O];

    const int tid    = threadIdx.x;
    const int warpId = tid >> 5;
    const int lane   = tid & 31;

    const int x0 = blockIdx.x * TW;
    const int y0 = blockIdx.y * TH;

    // ---- phase 0: build CSR in smem (ONCE per CTA) ----
    if (tid < O) { s_cnt[tid] = 0; s_cur[tid] = 0; }

    int4  w0 = make_int4(0, 0, 0, 0), w1 = w0;
    float v0 = 0.0f, v1 = 0.0f;
    const bool h0 = (tid < nnz);
    const bool h1 = (tid + 1024 < nnz);
    if (h0) { w0 = wi4[tid];        v0 = wv[tid]; }
    if (h1) { w1 = wi4[tid + 1024]; v1 = wv[tid + 1024]; }
    __syncthreads();                       // zeroing visible

    if (h0) atomicAdd(&s_cnt[w0.x], 1);
    if (h1) atomicAdd(&s_cnt[w1.x], 1);
    __syncthreads();                       // counts complete

    // exclusive scan of 256 even-padded counts (warp 0)
    if (tid < 32) {
        int base = tid * 8;
        int loc[8], run = 0;
#pragma unroll
        for (int j = 0; j < 8; j++) {
            int c = (s_cnt[base + j] + 1) & ~1;   // pad to even
            loc[j] = run; run += c;
        }
        int incl = run;
#pragma unroll
        for (int d = 1; d < 32; d <<= 1) {
            int n = __shfl_up_sync(0xffffffffu, incl, d);
            if (tid >= d) incl += n;
        }
        int excl = incl - run;
#pragma unroll
        for (int j = 0; j < 8; j++) s_off[base + j] = excl + loc[j];
        if (tid == 31) s_off[O] = incl;
    }
    __syncthreads();                       // s_off ready

    // scatter entries (with reference flatten-mismatch remap)
    if (h0) {
        int k  = w0.y * (KW * C) + w0.z * C + w0.w;  // flat idx in W.reshape(O,-1)
        int ce = k / 9;
        int t  = k - 9 * ce;
        int dy = t / 3;
        int dx = t - 3 * dy;
        int off = (dy * C + ce) * XP + dx;
        int pos = s_off[w0.x] + atomicAdd(&s_cur[w0.x], 1);
        s_csr[pos] = make_uint2((unsigned)off, __float_as_uint(v0));
    }
    if (h1) {
        int k  = w1.y * (KW * C) + w1.z * C + w1.w;
        int ce = k / 9;
        int t  = k - 9 * ce;
        int dy = t / 3;
        int dx = t - 3 * dy;
        int off = (dy * C + ce) * XP + dx;
        int pos = s_off[w1.x] + atomicAdd(&s_cur[w1.x], 1);
        s_csr[pos] = make_uint2((unsigned)off, __float_as_uint(v1));
    }
    if (tid < O) {                          // zero the pad slot per bucket
        int c = s_cnt[tid];
        if (c & 1) s_csr[s_off[tid] + c] = make_uint2(0u, 0u);
    }
    // (sync at top of batch loop covers CSR visibility)

    const int oBase = warpId * 8;
    const float* s_in_lane = s_in + lane;
    const int och  = tid & 255;
    const int pgrp = tid >> 8;             // 0..3

    // ================= persistent batch loop =================
    for (int bz = 0; bz < B; bz++) {

        // ---- stage input tile [row][c][x], one pixel/warp-iter ----
        // ROWS*XT = 204 pixels, 32 warps -> 7 iterations (last partial)
#pragma unroll
        for (int t = 0; t < 7; t++) {
            int p = warpId + (t << 5);
            if (p < ROWS * XT) {
                int rr = p / XT;
                int xx = p - rr * XT;
                int iy = y0 + rr;
                int ix = x0 + xx;
                float* sb = s_in + (rr * C + lane) * XP + xx;
                if ((iy < H) && (ix < W)) {
                    const float* gb = in + (((bz * H + iy) * W + ix) * C) + lane;
                    float v[8];
#pragma unroll
                    for (int cg = 0; cg < 8; cg++) v[cg] = gb[cg * 32];
#pragma unroll
                    for (int cg = 0; cg < 8; cg++) sb[cg * 32 * XP] = v[cg];
                } else {
#pragma unroll
                    for (int cg = 0; cg < 8; cg++) sb[cg * 32 * XP] = 0.0f;
                }
            }
        }
        __syncthreads();     // CSR (first iter) + staged tile ready

        // ---- gather-accumulate: 8 o per warp, lane = x ----
        float acc[8][TH];
#pragma unroll
        for (int oo = 0; oo < 8; oo++)
#pragma unroll
            for (int r = 0; r < TH; r++) acc[oo][r] = 0.0f;

#pragma unroll
        for (int oo = 0; oo < 8; oo++) {
            const int k0 = s_off[oBase + oo];
            const int k1 = s_off[oBase + oo + 1];
#pragma unroll 2
            for (int k = k0; k < k1; k += 2) {
                uint4 e = *(const uint4*)(s_csr + k);    // 2 entries, 16B aligned
                const float* a0 = s_in_lane + e.x;
                const float* a1 = s_in_lane + e.z;
                float d0[TH], d1[TH];
#pragma unroll
                for (int r = 0; r < TH; r++) d0[r] = a0[r * RPITCH];
#pragma unroll
                for (int r = 0; r < TH; r++) d1[r] = a1[r * RPITCH];
                const float f0 = __uint_as_float(e.y);
                const float f1 = __uint_as_float(e.w);
#pragma unroll
                for (int r = 0; r < TH; r++) acc[oo][r] = fmaf(f0, d0[r], acc[oo][r]);
#pragma unroll
                for (int r = 0; r < TH; r++) acc[oo][r] = fmaf(f1, d1[r], acc[oo][r]);
            }
        }
        __syncthreads();   // s_in dead -> reuse for transpose

        // ---- transpose-stage and coalesced store ----
        float* s_out = s_in;  // [r][o][x], pitch TWP=33
#pragma unroll
        for (int oo = 0; oo < 8; oo++) {
            int o = oBase + oo;
#pragma unroll
            for (int r = 0; r < TH; r++)
                s_out[(r * O + o) * TWP + lane] = acc[oo][r];
        }
        __syncthreads();

        const int obase32 = ((bz * OH + y0) * OW + x0) * O + och;
#pragma unroll
        for (int i = 0; i < 32; i++) {
            int p  = pgrp + (i << 2);          // 0..127
            int r  = p >> 5;
            int xx = p & 31;
            int gy = y0 + r;
            int gx = x0 + xx;
            if (gy < OH && gx < OW)
                out[obase32 + (r * OW + xx) * O] =
                    s_out[(r * O + och) * TWP + xx];
        }
        __syncthreads();   // s_out dead before next batch's staging
    }
}

// ============================================================
extern "C" void kernel_launch(void* const* d_in, const int* in_sizes, int n_in,
                              void* d_out, int out_size)
{
    const float* in  = (const float*)d_in[0];
    const int4*  wi4 = (const int4*)d_in[1];   // int32 indices, 4 per entry
    const float* wv  = (const float*)d_in[2];
    float*       out = (float*)d_out;

    int nnz = in_sizes[2];
    if (nnz > 2048) nnz = 2048;
    int B = in_sizes[0] / (H * W * C);

    cudaFuncSetAttribute(sparse_conv_kernel,
                         cudaFuncAttributeMaxDynamicSharedMemorySize, SMEM_BYTES);

    dim3 grid((OW + TW - 1) / TW, (OH + TH - 1) / TH, 1);   // 4 x 32 = 128 CTAs
    sparse_conv_kernel<<<grid, 1024, SMEM_BYTES>>>(in, wi4, wv, out, nnz, B);
}